// round 8
// baseline (speedup 1.0000x reference)
#include <cuda_runtime.h>
#include <cuda_bf16.h>
#include <math.h>
#include <stdint.h>

// Problem constants
#define NN 50000
#define NE 800000
#define DD 128
#define NC 2
#define SCAN_T 1024
#define SCAN_CH 49   // ceil(NN / SCAN_T)
#define AS 136       // smem row stride in bf16 elems (128 + 8 pad: conflict-free ldmatrix)
#define GR 256       // rows per GEMM block
#define GT 512       // threads per GEMM block (16 warps)

// ---------------- scratch (static device memory; no allocation) ----------------
__device__ int   g_cnt[NN];        // in-degree (edges only) -- zeroed by edge2 tail
__device__ int   g_offs[NN + 1];   // CSR row offsets
__device__ int   g_cursor[NN];     // scatter cursors
__device__ int2  g_adj[NE];        // (src, coef bits) per CSR slot
__device__ float g_inv[NN];        // deg^{-1/2} (deg includes self loop)
__device__ __align__(16) __nv_bfloat16 g_hb[NN * DD];  // GEMM output (bf16)
__device__ __align__(16) __nv_bfloat16 g_ab[NN * DD];  // post-ReLU activations (bf16)
__device__ float g_pool[DD];       // column sums for mean pool -- zeroed by finalize tail

// ---------------- count in-degrees over dst (int) ----------------
__global__ void k_count(const int* __restrict__ dst, int* __restrict__ cnt) {
    int e = blockIdx.x * blockDim.x + threadIdx.x;
    if (e < NE) atomicAdd(&cnt[dst[e]], 1);
}

// ---------------- single-block scan: offs, cursor, inv ----------------
__global__ void __launch_bounds__(SCAN_T)
k_scan(const int* __restrict__ cnt, int* __restrict__ offs,
       int* __restrict__ cursor, float* __restrict__ inv) {
    __shared__ int ssum[SCAN_T];
    int t = threadIdx.x;
    int c0 = t * SCAN_CH;
    int c1 = min(c0 + SCAN_CH, NN);
    int s = 0;
    for (int i = c0; i < c1; i++) s += cnt[i];
    ssum[t] = s;
    __syncthreads();
    for (int off = 1; off < SCAN_T; off <<= 1) {
        int u = (t >= off) ? ssum[t - off] : 0;
        __syncthreads();
        ssum[t] += u;
        __syncthreads();
    }
    int run = ssum[t] - s;   // exclusive prefix for this chunk
    for (int i = c0; i < c1; i++) {
        offs[i] = run;
        cursor[i] = run;
        inv[i] = rsqrtf((float)cnt[i] + 1.0f);
        run += cnt[i];
    }
    if (t == SCAN_T - 1) offs[NN] = NE;
}

// ---------------- scatter edges into CSR bins, precompute coef ----------------
__global__ void k_scatter(const int* __restrict__ src, const int* __restrict__ dst,
                          const float* __restrict__ inv,
                          int* __restrict__ cursor, int2* __restrict__ adj) {
    int e = blockIdx.x * blockDim.x + threadIdx.x;
    if (e >= NE) return;
    int s = src[e], d = dst[e];
    int pos = atomicAdd(&cursor[d], 1);
    adj[pos] = make_int2(s, __float_as_int(inv[s] * inv[d]));
}

// ---------------- PTX helpers ----------------
__device__ __forceinline__ uint32_t s2u(const void* p) {
    uint32_t a;
    asm("{ .reg .u64 t; cvta.to.shared.u64 t, %1; cvt.u32.u64 %0, t; }"
        : "=r"(a) : "l"(p));
    return a;
}
__device__ __forceinline__ void ldmA(uint32_t& a0, uint32_t& a1, uint32_t& a2, uint32_t& a3,
                                     uint32_t addr) {
    asm volatile("ldmatrix.sync.aligned.m8n8.x4.shared.b16 {%0,%1,%2,%3}, [%4];"
                 : "=r"(a0), "=r"(a1), "=r"(a2), "=r"(a3) : "r"(addr));
}
__device__ __forceinline__ void ldmB(uint32_t& b0, uint32_t& b1, uint32_t addr) {
    asm volatile("ldmatrix.sync.aligned.m8n8.x2.trans.shared.b16 {%0,%1}, [%2];"
                 : "=r"(b0), "=r"(b1) : "r"(addr));
}
__device__ __forceinline__ void mma16816(float* c, uint32_t a0, uint32_t a1, uint32_t a2,
                                         uint32_t a3, uint32_t b0, uint32_t b1) {
    asm volatile("mma.sync.aligned.m16n8k16.row.col.f32.bf16.bf16.f32 "
                 "{%0,%1,%2,%3}, {%4,%5,%6,%7}, {%8,%9}, {%0,%1,%2,%3};"
                 : "+f"(c[0]), "+f"(c[1]), "+f"(c[2]), "+f"(c[3])
                 : "r"(a0), "r"(a1), "r"(a2), "r"(a3), "r"(b0), "r"(b1));
}

// ---------------- GEMM via HMMA: HB[n,128] = bf16(A[n,128] @ W[128,128]) -------
// Block: 256 rows, 512 threads (16 warps). Warp w: rows w*16..+15, all 128 cols.
// smem: W row-major bf16 [k][AS], A rows bf16 [r][AS]. Fragments via ldmatrix.
template<typename IT>
__global__ void __launch_bounds__(GT, 2)
k_gemm_mma(const IT* __restrict__ A, const float* __restrict__ W,
           __nv_bfloat16* __restrict__ HB, int n) {
    extern __shared__ __nv_bfloat16 smb[];
    __nv_bfloat16* wsm = smb;             // [DD][AS]
    __nv_bfloat16* asmem = smb + DD * AS; // [GR][AS]

    const int tid  = threadIdx.x;
    const int lane = tid & 31;
    const int w    = tid >> 5;
    const int row0 = blockIdx.x * GR;

    // W fp32 -> bf16 smem, row-major, coalesced
    for (int i = tid * 4; i < DD * DD; i += GT * 4) {
        float4 v = *(const float4*)&W[i];
        int k = i >> 7, nn = i & 127;
        __nv_bfloat162* p = (__nv_bfloat162*)&wsm[k * AS + nn];
        p[0] = __floats2bfloat162_rn(v.x, v.y);
        p[1] = __floats2bfloat162_rn(v.z, v.w);
    }
    // A rows -> bf16 smem
    if (sizeof(IT) == 4) {
        for (int i = tid * 4; i < GR * DD; i += GT * 4) {
            int r = i >> 7, k = i & 127;
            float4 v = make_float4(0.f, 0.f, 0.f, 0.f);
            if (row0 + r < n) v = *(const float4*)&((const float*)A)[(size_t)(row0 + r) * DD + k];
            __nv_bfloat162* p = (__nv_bfloat162*)&asmem[r * AS + k];
            p[0] = __floats2bfloat162_rn(v.x, v.y);
            p[1] = __floats2bfloat162_rn(v.z, v.w);
        }
    } else {
        for (int i = tid * 8; i < GR * DD; i += GT * 8) {
            int r = i >> 7, k = i & 127;
            uint4 v = make_uint4(0u, 0u, 0u, 0u);
            if (row0 + r < n) v = *(const uint4*)&((const __nv_bfloat16*)A)[(size_t)(row0 + r) * DD + k];
            *(uint4*)&asmem[r * AS + k] = v;
        }
    }
    __syncthreads();

    const int g = lane >> 2, t = lane & 3;
    // ldmatrix source addresses
    const int arow = w * 16 + (lane & 15);
    const int acol = (lane >> 4) * 8;
    const uint32_t a_base = s2u(&asmem[arow * AS + acol]);
    const int brow = lane & 15;
    const uint32_t b_base = s2u(&wsm[brow * AS]);

    float acc[16][4];
    #pragma unroll
    for (int nt = 0; nt < 16; nt++)
        #pragma unroll
        for (int j = 0; j < 4; j++) acc[nt][j] = 0.f;

    #pragma unroll
    for (int kc = 0; kc < 8; kc++) {
        uint32_t a0, a1, a2, a3;
        ldmA(a0, a1, a2, a3, a_base + kc * 32);          // +16 bf16 per chunk
        uint32_t bchunk = b_base + kc * 16 * AS * 2;     // +16 rows per chunk
        #pragma unroll
        for (int nt = 0; nt < 16; nt++) {
            uint32_t b0, b1;
            ldmB(b0, b1, bchunk + nt * 16);              // +8 bf16 per n-tile
            mma16816(acc[nt], a0, a1, a2, a3, b0, b1);
        }
    }

    // store C: c0,c1 -> row g cols 2t,2t+1 ; c2,c3 -> row g+8
    const int r1 = row0 + w * 16 + g;
    const int r2 = r1 + 8;
    #pragma unroll
    for (int nt = 0; nt < 16; nt++) {
        int col = nt * 8 + t * 2;
        if (r1 < n)
            *(__nv_bfloat162*)&HB[(size_t)r1 * DD + col] =
                __floats2bfloat162_rn(acc[nt][0], acc[nt][1]);
        if (r2 < n)
            *(__nv_bfloat162*)&HB[(size_t)r2 * DD + col] =
                __floats2bfloat162_rn(acc[nt][2], acc[nt][3]);
    }
}

// ---------------- bf16 row fragment -> float4 ----------------
__device__ __forceinline__ float4 bf2f4(uint2 u) {
    __nv_bfloat162 a = *reinterpret_cast<__nv_bfloat162*>(&u.x);
    __nv_bfloat162 b = *reinterpret_cast<__nv_bfloat162*>(&u.y);
    float2 fa = __bfloat1622float2(a);
    float2 fb = __bfloat1622float2(b);
    return make_float4(fa.x, fa.y, fb.x, fb.y);
}

// ---------------- CSR edge aggregation (direct uniform ldg, 8-wide unroll) ----
__device__ __forceinline__ float4 agg_node(
    int d, int lane,
    const int* __restrict__ offs, const int2* __restrict__ adj,
    const __nv_bfloat16* __restrict__ hb, const float* __restrict__ inv)
{
    float invd = inv[d];
    float selfc = invd * invd;
    float4 sv = bf2f4(*(const uint2*)&hb[d * DD + lane * 4]);
    float ax = sv.x * selfc, ay = sv.y * selfc, az = sv.z * selfc, aw = sv.w * selfc;
    float bx = 0.f, by = 0.f, bz = 0.f, bw = 0.f;

    int beg = offs[d], end = offs[d + 1];
    int i = beg;
    for (; i + 7 < end; i += 8) {
        int2 e0 = __ldg(&adj[i]);
        int2 e1 = __ldg(&adj[i + 1]);
        int2 e2 = __ldg(&adj[i + 2]);
        int2 e3 = __ldg(&adj[i + 3]);
        int2 e4 = __ldg(&adj[i + 4]);
        int2 e5 = __ldg(&adj[i + 5]);
        int2 e6 = __ldg(&adj[i + 6]);
        int2 e7 = __ldg(&adj[i + 7]);
        uint2 r0 = *(const uint2*)&hb[e0.x * DD + lane * 4];
        uint2 r1 = *(const uint2*)&hb[e1.x * DD + lane * 4];
        uint2 r2 = *(const uint2*)&hb[e2.x * DD + lane * 4];
        uint2 r3 = *(const uint2*)&hb[e3.x * DD + lane * 4];
        uint2 r4 = *(const uint2*)&hb[e4.x * DD + lane * 4];
        uint2 r5 = *(const uint2*)&hb[e5.x * DD + lane * 4];
        uint2 r6 = *(const uint2*)&hb[e6.x * DD + lane * 4];
        uint2 r7 = *(const uint2*)&hb[e7.x * DD + lane * 4];
        float4 v; float c;
        c = __int_as_float(e0.y); v = bf2f4(r0);
        ax += c * v.x; ay += c * v.y; az += c * v.z; aw += c * v.w;
        c = __int_as_float(e1.y); v = bf2f4(r1);
        bx += c * v.x; by += c * v.y; bz += c * v.z; bw += c * v.w;
        c = __int_as_float(e2.y); v = bf2f4(r2);
        ax += c * v.x; ay += c * v.y; az += c * v.z; aw += c * v.w;
        c = __int_as_float(e3.y); v = bf2f4(r3);
        bx += c * v.x; by += c * v.y; bz += c * v.z; bw += c * v.w;
        c = __int_as_float(e4.y); v = bf2f4(r4);
        ax += c * v.x; ay += c * v.y; az += c * v.z; aw += c * v.w;
        c = __int_as_float(e5.y); v = bf2f4(r5);
        bx += c * v.x; by += c * v.y; bz += c * v.z; bw += c * v.w;
        c = __int_as_float(e6.y); v = bf2f4(r6);
        ax += c * v.x; ay += c * v.y; az += c * v.z; aw += c * v.w;
        c = __int_as_float(e7.y); v = bf2f4(r7);
        bx += c * v.x; by += c * v.y; bz += c * v.z; bw += c * v.w;
    }
    for (; i + 1 < end; i += 2) {
        int2 e0 = __ldg(&adj[i]);
        int2 e1 = __ldg(&adj[i + 1]);
        uint2 r0 = *(const uint2*)&hb[e0.x * DD + lane * 4];
        uint2 r1 = *(const uint2*)&hb[e1.x * DD + lane * 4];
        float c0 = __int_as_float(e0.y), c1 = __int_as_float(e1.y);
        float4 v0 = bf2f4(r0), v1 = bf2f4(r1);
        ax += c0 * v0.x; ay += c0 * v0.y; az += c0 * v0.z; aw += c0 * v0.w;
        bx += c1 * v1.x; by += c1 * v1.y; bz += c1 * v1.z; bw += c1 * v1.w;
    }
    if (i < end) {
        int2 e0 = __ldg(&adj[i]);
        float c0 = __int_as_float(e0.y);
        float4 v0 = bf2f4(*(const uint2*)&hb[e0.x * DD + lane * 4]);
        ax += c0 * v0.x; ay += c0 * v0.y; az += c0 * v0.z; aw += c0 * v0.w;
    }
    return make_float4(ax + bx, ay + by, az + bz, aw + bw);
}

// ---------------- layer 1: ab = bf16(relu(aggregate + b1)) ----------------
__global__ void __launch_bounds__(256)
k_edge1(const int* __restrict__ offs, const int2* __restrict__ adj,
        const __nv_bfloat16* __restrict__ hb,
        const float* __restrict__ inv, const float* __restrict__ b,
        __nv_bfloat16* __restrict__ out) {
    int warp = (blockIdx.x * blockDim.x + threadIdx.x) >> 5;
    if (warp >= NN) return;
    int lane = threadIdx.x & 31;
    float4 a = agg_node(warp, lane, offs, adj, hb, inv);
    float4 bb = ((const float4*)b)[lane];
    uint2 ob;
    __nv_bfloat162 p0 = __floats2bfloat162_rn(fmaxf(a.x + bb.x, 0.f), fmaxf(a.y + bb.y, 0.f));
    __nv_bfloat162 p1 = __floats2bfloat162_rn(fmaxf(a.z + bb.z, 0.f), fmaxf(a.w + bb.w, 0.f));
    ob.x = *reinterpret_cast<unsigned int*>(&p0);
    ob.y = *reinterpret_cast<unsigned int*>(&p1);
    *(uint2*)&out[(size_t)warp * DD + lane * 4] = ob;
}

// ---------------- layer 2: pool += relu(aggregate + b2); also zero cnt --------
__global__ void __launch_bounds__(256)
k_edge2_pool(const int* __restrict__ offs, const int2* __restrict__ adj,
             const __nv_bfloat16* __restrict__ hb,
             const float* __restrict__ inv, const float* __restrict__ b,
             float* __restrict__ pool, int* __restrict__ cnt) {
    __shared__ float ps[DD];
    int tid = threadIdx.x;
    if (tid < DD) ps[tid] = 0.0f;
    __syncthreads();

    int gt = blockIdx.x * blockDim.x + tid;
    if (gt < NN) cnt[gt] = 0;    // reset for next graph replay

    int warp = gt >> 5;
    int lane = tid & 31;
    if (warp < NN) {
        float4 a = agg_node(warp, lane, offs, adj, hb, inv);
        float4 bb = ((const float4*)b)[lane];
        atomicAdd(&ps[lane * 4 + 0], fmaxf(a.x + bb.x, 0.f));
        atomicAdd(&ps[lane * 4 + 1], fmaxf(a.y + bb.y, 0.f));
        atomicAdd(&ps[lane * 4 + 2], fmaxf(a.z + bb.z, 0.f));
        atomicAdd(&ps[lane * 4 + 3], fmaxf(a.w + bb.w, 0.f));
    }
    __syncthreads();
    if (tid < DD) atomicAdd(&pool[tid], ps[tid]);
}

// ---------------- finalize: logits + log_softmax; also zero pool ----------------
__global__ void k_finalize(float* __restrict__ pool, const float* __restrict__ Wc,
                           const float* __restrict__ bc, float* __restrict__ out) {
    int t = threadIdx.x;             // 0..31
    float l0 = 0.f, l1 = 0.f;
    const float invn = 1.0f / (float)NN;
    #pragma unroll
    for (int j = 0; j < 4; j++) {
        int c = t * 4 + j;
        float g = pool[c] * invn;
        l0 += g * Wc[c * NC + 0];
        l1 += g * Wc[c * NC + 1];
        pool[c] = 0.0f;              // reset for next graph replay
    }
    #pragma unroll
    for (int o = 16; o > 0; o >>= 1) {
        l0 += __shfl_down_sync(0xFFFFFFFFu, l0, o);
        l1 += __shfl_down_sync(0xFFFFFFFFu, l1, o);
    }
    if (t == 0) {
        l0 += bc[0];
        l1 += bc[1];
        float m = fmaxf(l0, l1);
        float lse = m + logf(expf(l0 - m) + expf(l1 - m));
        out[0] = l0 - lse;
        out[1] = l1 - lse;
    }
}

// ---------------- launch ----------------
extern "C" void kernel_launch(void* const* d_in, const int* in_sizes, int n_in,
                              void* d_out, int out_size) {
    const float* x  = (const float*)d_in[0];
    const int*   ei = (const int*)d_in[1];
    const float* W1 = (const float*)d_in[2];
    const float* b1 = (const float*)d_in[3];
    const float* W2 = (const float*)d_in[4];
    const float* b2 = (const float*)d_in[5];
    const float* Wc = (const float*)d_in[6];
    const float* bc = (const float*)d_in[7];
    float* out = (float*)d_out;

    const int* src = ei;
    const int* dst = ei + NE;

    int *cnt, *offs, *cursor;
    int2* adj;
    float *inv, *pool;
    __nv_bfloat16 *hb, *ab;
    cudaGetSymbolAddress((void**)&cnt,    g_cnt);
    cudaGetSymbolAddress((void**)&offs,   g_offs);
    cudaGetSymbolAddress((void**)&cursor, g_cursor);
    cudaGetSymbolAddress((void**)&adj,    g_adj);
    cudaGetSymbolAddress((void**)&inv,    g_inv);
    cudaGetSymbolAddress((void**)&hb,     g_hb);
    cudaGetSymbolAddress((void**)&ab,     g_ab);
    cudaGetSymbolAddress((void**)&pool,   g_pool);

    const int smem = (DD + GR) * AS * (int)sizeof(__nv_bfloat16);
    cudaFuncSetAttribute(k_gemm_mma<float>, cudaFuncAttributeMaxDynamicSharedMemorySize, smem);
    cudaFuncSetAttribute(k_gemm_mma<__nv_bfloat16>, cudaFuncAttributeMaxDynamicSharedMemorySize, smem);

    const int gemm_grid = (NN + GR - 1) / GR;
    const int edge_grid = (NN * 32 + 255) / 256;

    // CSR build + normalization (cnt pre-zeroed: static init / previous replay)
    k_count<<<(NE + 255) / 256, 256>>>(dst, cnt);
    k_scan<<<1, SCAN_T>>>(cnt, offs, cursor, inv);
    k_scatter<<<(NE + 255) / 256, 256>>>(src, dst, inv, cursor, adj);

    // layer 1  (launch idx 3 = profiled kernel)
    k_gemm_mma<float><<<gemm_grid, GT, smem>>>(x, W1, hb, NN);
    k_edge1<<<edge_grid, 256>>>(offs, adj, hb, inv, b1, ab);

    // layer 2
    k_gemm_mma<__nv_bfloat16><<<gemm_grid, GT, smem>>>(ab, W2, hb, NN);
    k_edge2_pool<<<edge_grid, 256>>>(offs, adj, hb, inv, b2, pool, cnt);

    // classifier + log_softmax
    k_finalize<<<1, 32>>>(pool, Wc, bc, out);
}

// round 9
// speedup vs baseline: 1.1005x; 1.1005x over previous
#include <cuda_runtime.h>
#include <cuda_bf16.h>
#include <math.h>
#include <stdint.h>

// Problem constants
#define NN 50000
#define NE 800000
#define DD 128
#define NC 2
#define SCAN_T 1024
#define SCAN_CH 49   // ceil(NN / SCAN_T)
#define AS 136       // smem row stride in bf16 elems (128 + 8 pad: conflict-free ldmatrix)
#define GR 128       // rows per GEMM block
#define GT 256       // threads per GEMM block (8 warps)

// ---------------- scratch (static device memory; no allocation) ----------------
__device__ int   g_cnt[NN];        // in-degree (edges only) -- zeroed by edge2 tail
__device__ int   g_offs[NN + 1];   // CSR row offsets
__device__ int   g_cursor[NN];     // scatter cursors
__device__ int2  g_adj[NE];        // (src, coef bits) per CSR slot
__device__ float g_inv[NN];        // deg^{-1/2} (deg includes self loop)
__device__ __align__(16) __nv_bfloat16 g_hb[NN * DD];  // GEMM output (bf16)
__device__ __align__(16) __nv_bfloat16 g_ab[NN * DD];  // post-ReLU activations (bf16)
__device__ float g_pool[DD];       // column sums for mean pool -- zeroed by finalize tail

// ---------------- count in-degrees over dst (int) ----------------
__global__ void k_count(const int* __restrict__ dst, int* __restrict__ cnt) {
    int e = blockIdx.x * blockDim.x + threadIdx.x;
    if (e < NE) atomicAdd(&cnt[dst[e]], 1);
}

// ---------------- single-block scan: offs, cursor, inv ----------------
__global__ void __launch_bounds__(SCAN_T)
k_scan(const int* __restrict__ cnt, int* __restrict__ offs,
       int* __restrict__ cursor, float* __restrict__ inv) {
    __shared__ int ssum[SCAN_T];
    int t = threadIdx.x;
    int c0 = t * SCAN_CH;
    int c1 = min(c0 + SCAN_CH, NN);
    int s = 0;
    for (int i = c0; i < c1; i++) s += cnt[i];
    ssum[t] = s;
    __syncthreads();
    for (int off = 1; off < SCAN_T; off <<= 1) {
        int u = (t >= off) ? ssum[t - off] : 0;
        __syncthreads();
        ssum[t] += u;
        __syncthreads();
    }
    int run = ssum[t] - s;   // exclusive prefix for this chunk
    for (int i = c0; i < c1; i++) {
        offs[i] = run;
        cursor[i] = run;
        inv[i] = rsqrtf((float)cnt[i] + 1.0f);
        run += cnt[i];
    }
    if (t == SCAN_T - 1) offs[NN] = NE;
}

// ---------------- scatter edges into CSR bins, precompute coef ----------------
__global__ void k_scatter(const int* __restrict__ src, const int* __restrict__ dst,
                          const float* __restrict__ inv,
                          int* __restrict__ cursor, int2* __restrict__ adj) {
    int e = blockIdx.x * blockDim.x + threadIdx.x;
    if (e >= NE) return;
    int s = src[e], d = dst[e];
    int pos = atomicAdd(&cursor[d], 1);
    adj[pos] = make_int2(s, __float_as_int(inv[s] * inv[d]));
}

// ---------------- PTX helpers ----------------
__device__ __forceinline__ uint32_t s2u(const void* p) {
    uint32_t a;
    asm("{ .reg .u64 t; cvta.to.shared.u64 t, %1; cvt.u32.u64 %0, t; }"
        : "=r"(a) : "l"(p));
    return a;
}
__device__ __forceinline__ void ldmA(uint32_t& a0, uint32_t& a1, uint32_t& a2, uint32_t& a3,
                                     uint32_t addr) {
    asm volatile("ldmatrix.sync.aligned.m8n8.x4.shared.b16 {%0,%1,%2,%3}, [%4];"
                 : "=r"(a0), "=r"(a1), "=r"(a2), "=r"(a3) : "r"(addr));
}
__device__ __forceinline__ void ldmBT4(uint32_t& b0, uint32_t& b1, uint32_t& b2, uint32_t& b3,
                                       uint32_t addr) {
    asm volatile("ldmatrix.sync.aligned.m8n8.x4.trans.shared.b16 {%0,%1,%2,%3}, [%4];"
                 : "=r"(b0), "=r"(b1), "=r"(b2), "=r"(b3) : "r"(addr));
}
__device__ __forceinline__ void mma16816(float* c, uint32_t a0, uint32_t a1, uint32_t a2,
                                         uint32_t a3, uint32_t b0, uint32_t b1) {
    asm volatile("mma.sync.aligned.m16n8k16.row.col.f32.bf16.bf16.f32 "
                 "{%0,%1,%2,%3}, {%4,%5,%6,%7}, {%8,%9}, {%0,%1,%2,%3};"
                 : "+f"(c[0]), "+f"(c[1]), "+f"(c[2]), "+f"(c[3])
                 : "r"(a0), "r"(a1), "r"(a2), "r"(a3), "r"(b0), "r"(b1));
}

// ---------------- GEMM via HMMA, B register-resident ---------------------------
// Block: 128 rows, 256 threads (8 warps) = 2 row-groups x 4 col-strips (32 cols).
// Each warp loads its B strip ONCE into 64 regs (16 ldmatrix.x4.trans),
// then streams 4 row-tiles of 16: per tile 8 ldmA + 32 mma, acc = 16 regs.
template<typename IT>
__global__ void __launch_bounds__(GT, 2)
k_gemm_mma(const IT* __restrict__ A, const float* __restrict__ W,
           __nv_bfloat16* __restrict__ HB, int n) {
    extern __shared__ __nv_bfloat16 smb[];
    __nv_bfloat16* wsm = smb;             // [DD][AS]
    __nv_bfloat16* asmem = smb + DD * AS; // [GR][AS]

    const int tid  = threadIdx.x;
    const int lane = tid & 31;
    const int w    = tid >> 5;
    const int row0 = blockIdx.x * GR;

    // W fp32 -> bf16 smem, row-major, coalesced
    for (int i = tid * 4; i < DD * DD; i += GT * 4) {
        float4 v = *(const float4*)&W[i];
        int k = i >> 7, nn = i & 127;
        __nv_bfloat162* p = (__nv_bfloat162*)&wsm[k * AS + nn];
        p[0] = __floats2bfloat162_rn(v.x, v.y);
        p[1] = __floats2bfloat162_rn(v.z, v.w);
    }
    // A rows -> bf16 smem
    if (sizeof(IT) == 4) {
        for (int i = tid * 4; i < GR * DD; i += GT * 4) {
            int r = i >> 7, k = i & 127;
            float4 v = make_float4(0.f, 0.f, 0.f, 0.f);
            if (row0 + r < n) v = *(const float4*)&((const float*)A)[(size_t)(row0 + r) * DD + k];
            __nv_bfloat162* p = (__nv_bfloat162*)&asmem[r * AS + k];
            p[0] = __floats2bfloat162_rn(v.x, v.y);
            p[1] = __floats2bfloat162_rn(v.z, v.w);
        }
    } else {
        for (int i = tid * 8; i < GR * DD; i += GT * 8) {
            int r = i >> 7, k = i & 127;
            uint4 v = make_uint4(0u, 0u, 0u, 0u);
            if (row0 + r < n) v = *(const uint4*)&((const __nv_bfloat16*)A)[(size_t)(row0 + r) * DD + k];
            *(uint4*)&asmem[r * AS + k] = v;
        }
    }
    __syncthreads();

    const int group = w >> 2;           // 0/1 : row half (64 rows each)
    const int strip = w & 3;            // 0..3 : 32-col strip
    const int col0  = strip * 32;
    const int g = lane >> 2, t = lane & 3;

    // ---- load B strip into registers: bf[kc][ntpair*4 + j] ----
    // x4.trans source: threads 0..15 -> rows k0..k15 at coloff, 16..31 -> coloff+8
    uint32_t bf[8][8];
    {
        const int brow = lane & 15;
        const int bco  = (lane >> 4) * 8;
        #pragma unroll
        for (int kc = 0; kc < 8; kc++) {
            uint32_t ad0 = s2u(&wsm[(kc * 16 + brow) * AS + col0 + bco]);
            ldmBT4(bf[kc][0], bf[kc][1], bf[kc][2], bf[kc][3], ad0);
            uint32_t ad1 = s2u(&wsm[(kc * 16 + brow) * AS + col0 + 16 + bco]);
            ldmBT4(bf[kc][4], bf[kc][5], bf[kc][6], bf[kc][7], ad1);
        }
    }

    const int alrow = (lane & 15);
    const int acol  = (lane >> 4) * 8;

    // ---- stream 4 row tiles of 16 rows ----
    #pragma unroll
    for (int rt = 0; rt < 4; rt++) {
        const int rbase = group * 64 + rt * 16;
        const uint32_t a_base = s2u(&asmem[(rbase + alrow) * AS + acol]);

        float acc[4][4];
        #pragma unroll
        for (int nt = 0; nt < 4; nt++)
            #pragma unroll
            for (int j = 0; j < 4; j++) acc[nt][j] = 0.f;

        #pragma unroll
        for (int kc = 0; kc < 8; kc++) {
            uint32_t a0, a1, a2, a3;
            ldmA(a0, a1, a2, a3, a_base + kc * 32);   // +16 bf16 per chunk
            #pragma unroll
            for (int nt = 0; nt < 4; nt++)
                mma16816(acc[nt], a0, a1, a2, a3, bf[kc][nt * 2], bf[kc][nt * 2 + 1]);
        }

        const int r1 = row0 + rbase + g;
        const int r2 = r1 + 8;
        #pragma unroll
        for (int nt = 0; nt < 4; nt++) {
            int col = col0 + nt * 8 + t * 2;
            if (r1 < n)
                *(__nv_bfloat162*)&HB[(size_t)r1 * DD + col] =
                    __floats2bfloat162_rn(acc[nt][0], acc[nt][1]);
            if (r2 < n)
                *(__nv_bfloat162*)&HB[(size_t)r2 * DD + col] =
                    __floats2bfloat162_rn(acc[nt][2], acc[nt][3]);
        }
    }
}

// ---------------- bf16 row fragment -> float4 ----------------
__device__ __forceinline__ float4 bf2f4(uint2 u) {
    __nv_bfloat162 a = *reinterpret_cast<__nv_bfloat162*>(&u.x);
    __nv_bfloat162 b = *reinterpret_cast<__nv_bfloat162*>(&u.y);
    float2 fa = __bfloat1622float2(a);
    float2 fb = __bfloat1622float2(b);
    return make_float4(fa.x, fa.y, fb.x, fb.y);
}

// ---------------- CSR edge aggregation (direct uniform ldg, 8-wide unroll) ----
__device__ __forceinline__ float4 agg_node(
    int d, int lane,
    const int* __restrict__ offs, const int2* __restrict__ adj,
    const __nv_bfloat16* __restrict__ hb, const float* __restrict__ inv)
{
    float invd = inv[d];
    float selfc = invd * invd;
    float4 sv = bf2f4(*(const uint2*)&hb[d * DD + lane * 4]);
    float ax = sv.x * selfc, ay = sv.y * selfc, az = sv.z * selfc, aw = sv.w * selfc;
    float bx = 0.f, by = 0.f, bz = 0.f, bw = 0.f;

    int beg = offs[d], end = offs[d + 1];
    int i = beg;
    for (; i + 7 < end; i += 8) {
        int2 e0 = __ldg(&adj[i]);
        int2 e1 = __ldg(&adj[i + 1]);
        int2 e2 = __ldg(&adj[i + 2]);
        int2 e3 = __ldg(&adj[i + 3]);
        int2 e4 = __ldg(&adj[i + 4]);
        int2 e5 = __ldg(&adj[i + 5]);
        int2 e6 = __ldg(&adj[i + 6]);
        int2 e7 = __ldg(&adj[i + 7]);
        uint2 r0 = *(const uint2*)&hb[e0.x * DD + lane * 4];
        uint2 r1 = *(const uint2*)&hb[e1.x * DD + lane * 4];
        uint2 r2 = *(const uint2*)&hb[e2.x * DD + lane * 4];
        uint2 r3 = *(const uint2*)&hb[e3.x * DD + lane * 4];
        uint2 r4 = *(const uint2*)&hb[e4.x * DD + lane * 4];
        uint2 r5 = *(const uint2*)&hb[e5.x * DD + lane * 4];
        uint2 r6 = *(const uint2*)&hb[e6.x * DD + lane * 4];
        uint2 r7 = *(const uint2*)&hb[e7.x * DD + lane * 4];
        float4 v; float c;
        c = __int_as_float(e0.y); v = bf2f4(r0);
        ax += c * v.x; ay += c * v.y; az += c * v.z; aw += c * v.w;
        c = __int_as_float(e1.y); v = bf2f4(r1);
        bx += c * v.x; by += c * v.y; bz += c * v.z; bw += c * v.w;
        c = __int_as_float(e2.y); v = bf2f4(r2);
        ax += c * v.x; ay += c * v.y; az += c * v.z; aw += c * v.w;
        c = __int_as_float(e3.y); v = bf2f4(r3);
        bx += c * v.x; by += c * v.y; bz += c * v.z; bw += c * v.w;
        c = __int_as_float(e4.y); v = bf2f4(r4);
        ax += c * v.x; ay += c * v.y; az += c * v.z; aw += c * v.w;
        c = __int_as_float(e5.y); v = bf2f4(r5);
        bx += c * v.x; by += c * v.y; bz += c * v.z; bw += c * v.w;
        c = __int_as_float(e6.y); v = bf2f4(r6);
        ax += c * v.x; ay += c * v.y; az += c * v.z; aw += c * v.w;
        c = __int_as_float(e7.y); v = bf2f4(r7);
        bx += c * v.x; by += c * v.y; bz += c * v.z; bw += c * v.w;
    }
    for (; i + 1 < end; i += 2) {
        int2 e0 = __ldg(&adj[i]);
        int2 e1 = __ldg(&adj[i + 1]);
        uint2 r0 = *(const uint2*)&hb[e0.x * DD + lane * 4];
        uint2 r1 = *(const uint2*)&hb[e1.x * DD + lane * 4];
        float c0 = __int_as_float(e0.y), c1 = __int_as_float(e1.y);
        float4 v0 = bf2f4(r0), v1 = bf2f4(r1);
        ax += c0 * v0.x; ay += c0 * v0.y; az += c0 * v0.z; aw += c0 * v0.w;
        bx += c1 * v1.x; by += c1 * v1.y; bz += c1 * v1.z; bw += c1 * v1.w;
    }
    if (i < end) {
        int2 e0 = __ldg(&adj[i]);
        float c0 = __int_as_float(e0.y);
        float4 v0 = bf2f4(*(const uint2*)&hb[e0.x * DD + lane * 4]);
        ax += c0 * v0.x; ay += c0 * v0.y; az += c0 * v0.z; aw += c0 * v0.w;
    }
    return make_float4(ax + bx, ay + by, az + bz, aw + bw);
}

// ---------------- layer 1: ab = bf16(relu(aggregate + b1)) ----------------
__global__ void __launch_bounds__(256)
k_edge1(const int* __restrict__ offs, const int2* __restrict__ adj,
        const __nv_bfloat16* __restrict__ hb,
        const float* __restrict__ inv, const float* __restrict__ b,
        __nv_bfloat16* __restrict__ out) {
    int warp = (blockIdx.x * blockDim.x + threadIdx.x) >> 5;
    if (warp >= NN) return;
    int lane = threadIdx.x & 31;
    float4 a = agg_node(warp, lane, offs, adj, hb, inv);
    float4 bb = ((const float4*)b)[lane];
    uint2 ob;
    __nv_bfloat162 p0 = __floats2bfloat162_rn(fmaxf(a.x + bb.x, 0.f), fmaxf(a.y + bb.y, 0.f));
    __nv_bfloat162 p1 = __floats2bfloat162_rn(fmaxf(a.z + bb.z, 0.f), fmaxf(a.w + bb.w, 0.f));
    ob.x = *reinterpret_cast<unsigned int*>(&p0);
    ob.y = *reinterpret_cast<unsigned int*>(&p1);
    *(uint2*)&out[(size_t)warp * DD + lane * 4] = ob;
}

// ---------------- layer 2: pool += relu(aggregate + b2); also zero cnt --------
__global__ void __launch_bounds__(256)
k_edge2_pool(const int* __restrict__ offs, const int2* __restrict__ adj,
             const __nv_bfloat16* __restrict__ hb,
             const float* __restrict__ inv, const float* __restrict__ b,
             float* __restrict__ pool, int* __restrict__ cnt) {
    __shared__ float ps[DD];
    int tid = threadIdx.x;
    if (tid < DD) ps[tid] = 0.0f;
    __syncthreads();

    int gt = blockIdx.x * blockDim.x + tid;
    if (gt < NN) cnt[gt] = 0;    // reset for next graph replay

    int warp = gt >> 5;
    int lane = tid & 31;
    if (warp < NN) {
        float4 a = agg_node(warp, lane, offs, adj, hb, inv);
        float4 bb = ((const float4*)b)[lane];
        atomicAdd(&ps[lane * 4 + 0], fmaxf(a.x + bb.x, 0.f));
        atomicAdd(&ps[lane * 4 + 1], fmaxf(a.y + bb.y, 0.f));
        atomicAdd(&ps[lane * 4 + 2], fmaxf(a.z + bb.z, 0.f));
        atomicAdd(&ps[lane * 4 + 3], fmaxf(a.w + bb.w, 0.f));
    }
    __syncthreads();
    if (tid < DD) atomicAdd(&pool[tid], ps[tid]);
}

// ---------------- finalize: logits + log_softmax; also zero pool ----------------
__global__ void k_finalize(float* __restrict__ pool, const float* __restrict__ Wc,
                           const float* __restrict__ bc, float* __restrict__ out) {
    int t = threadIdx.x;             // 0..31
    float l0 = 0.f, l1 = 0.f;
    const float invn = 1.0f / (float)NN;
    #pragma unroll
    for (int j = 0; j < 4; j++) {
        int c = t * 4 + j;
        float g = pool[c] * invn;
        l0 += g * Wc[c * NC + 0];
        l1 += g * Wc[c * NC + 1];
        pool[c] = 0.0f;              // reset for next graph replay
    }
    #pragma unroll
    for (int o = 16; o > 0; o >>= 1) {
        l0 += __shfl_down_sync(0xFFFFFFFFu, l0, o);
        l1 += __shfl_down_sync(0xFFFFFFFFu, l1, o);
    }
    if (t == 0) {
        l0 += bc[0];
        l1 += bc[1];
        float m = fmaxf(l0, l1);
        float lse = m + logf(expf(l0 - m) + expf(l1 - m));
        out[0] = l0 - lse;
        out[1] = l1 - lse;
    }
}

// ---------------- launch ----------------
extern "C" void kernel_launch(void* const* d_in, const int* in_sizes, int n_in,
                              void* d_out, int out_size) {
    const float* x  = (const float*)d_in[0];
    const int*   ei = (const int*)d_in[1];
    const float* W1 = (const float*)d_in[2];
    const float* b1 = (const float*)d_in[3];
    const float* W2 = (const float*)d_in[4];
    const float* b2 = (const float*)d_in[5];
    const float* Wc = (const float*)d_in[6];
    const float* bc = (const float*)d_in[7];
    float* out = (float*)d_out;

    const int* src = ei;
    const int* dst = ei + NE;

    int *cnt, *offs, *cursor;
    int2* adj;
    float *inv, *pool;
    __nv_bfloat16 *hb, *ab;
    cudaGetSymbolAddress((void**)&cnt,    g_cnt);
    cudaGetSymbolAddress((void**)&offs,   g_offs);
    cudaGetSymbolAddress((void**)&cursor, g_cursor);
    cudaGetSymbolAddress((void**)&adj,    g_adj);
    cudaGetSymbolAddress((void**)&inv,    g_inv);
    cudaGetSymbolAddress((void**)&hb,     g_hb);
    cudaGetSymbolAddress((void**)&ab,     g_ab);
    cudaGetSymbolAddress((void**)&pool,   g_pool);

    const int smem = (DD + GR) * AS * (int)sizeof(__nv_bfloat16);
    cudaFuncSetAttribute(k_gemm_mma<float>, cudaFuncAttributeMaxDynamicSharedMemorySize, smem);
    cudaFuncSetAttribute(k_gemm_mma<__nv_bfloat16>, cudaFuncAttributeMaxDynamicSharedMemorySize, smem);

    const int gemm_grid = (NN + GR - 1) / GR;
    const int edge_grid = (NN * 32 + 255) / 256;

    // CSR build + normalization (cnt pre-zeroed: static init / previous replay)
    k_count<<<(NE + 255) / 256, 256>>>(dst, cnt);
    k_scan<<<1, SCAN_T>>>(cnt, offs, cursor, inv);
    k_scatter<<<(NE + 255) / 256, 256>>>(src, dst, inv, cursor, adj);

    // layer 1  (launch idx 3 = profiled kernel)
    k_gemm_mma<float><<<gemm_grid, GT, smem>>>(x, W1, hb, NN);
    k_edge1<<<edge_grid, 256>>>(offs, adj, hb, inv, b1, ab);

    // layer 2
    k_gemm_mma<__nv_bfloat16><<<gemm_grid, GT, smem>>>(ab, W2, hb, NN);
    k_edge2_pool<<<edge_grid, 256>>>(offs, adj, hb, inv, b2, pool, cnt);

    // classifier + log_softmax
    k_finalize<<<1, 32>>>(pool, Wc, bc, out);
}

// round 11
// speedup vs baseline: 1.1381x; 1.0342x over previous
#include <cuda_runtime.h>
#include <cuda_bf16.h>
#include <math.h>
#include <stdint.h>

// Problem constants
#define NN 50000
#define NE 800000
#define DD 128
#define NC 2
#define SCAN_T 1024
#define SCAN_CH 49   // ceil(NN / SCAN_T)
#define AS 136       // smem row stride in bf16 elems (128 + 8 pad: conflict-free ldmatrix)
#define GR 128       // rows per GEMM block
#define GT 256       // threads per GEMM block (8 warps)

// ---------------- scratch (static device memory; no allocation) ----------------
__device__ int   g_cnt[NN];        // in-degree (edges only) -- zeroed by edge2 tail
__device__ int   g_offs[NN + 1];   // CSR row offsets
__device__ int   g_cursor[NN];     // scatter cursors
__device__ int2  g_adj[NE];        // (src, coef bits) per CSR slot
__device__ float g_inv[NN];        // deg^{-1/2} (deg includes self loop)
__device__ __align__(16) __nv_bfloat16 g_hb[NN * DD];  // GEMM output (bf16)
__device__ __align__(16) __nv_bfloat16 g_ab[NN * DD];  // post-ReLU activations (bf16)
__device__ __align__(16) __nv_bfloat16 g_wb[DD * DD];  // W2 pre-converted to bf16
__device__ float g_pool[DD];       // column sums for mean pool -- zeroed by finalize tail

// ---------------- PTX helpers ----------------
__device__ __forceinline__ uint32_t s2u(const void* p) {
    uint32_t a;
    asm("{ .reg .u64 t; cvta.to.shared.u64 t, %1; cvt.u32.u64 %0, t; }"
        : "=r"(a) : "l"(p));
    return a;
}
__device__ __forceinline__ void ldmA(uint32_t& a0, uint32_t& a1, uint32_t& a2, uint32_t& a3,
                                     uint32_t addr) {
    asm volatile("ldmatrix.sync.aligned.m8n8.x4.shared.b16 {%0,%1,%2,%3}, [%4];"
                 : "=r"(a0), "=r"(a1), "=r"(a2), "=r"(a3) : "r"(addr));
}
__device__ __forceinline__ void ldmBT4(uint32_t& b0, uint32_t& b1, uint32_t& b2, uint32_t& b3,
                                       uint32_t addr) {
    asm volatile("ldmatrix.sync.aligned.m8n8.x4.trans.shared.b16 {%0,%1,%2,%3}, [%4];"
                 : "=r"(b0), "=r"(b1), "=r"(b2), "=r"(b3) : "r"(addr));
}
__device__ __forceinline__ void mma16816(float* c, uint32_t a0, uint32_t a1, uint32_t a2,
                                         uint32_t a3, uint32_t b0, uint32_t b1) {
    asm volatile("mma.sync.aligned.m16n8k16.row.col.f32.bf16.bf16.f32 "
                 "{%0,%1,%2,%3}, {%4,%5,%6,%7}, {%8,%9}, {%0,%1,%2,%3};"
                 : "+f"(c[0]), "+f"(c[1]), "+f"(c[2]), "+f"(c[3])
                 : "r"(a0), "r"(a1), "r"(a2), "r"(a3), "r"(b0), "r"(b1));
}

// ---------------- GEMM body (device fn): B register-resident HMMA --------------
// 128 rows/block, 8 warps = 2 row-groups x 4 col-strips. B strip loaded once
// into 64 regs; 4 row-tiles streamed: per tile 8 ldmA + 32 mma.
template<typename IT, typename WT>
__device__ __forceinline__ void gemm_body(
    int bid, __nv_bfloat16* smb,
    const IT* __restrict__ A, const WT* __restrict__ W,
    __nv_bfloat16* __restrict__ HB, int n)
{
    __nv_bfloat16* wsm = smb;             // [DD][AS]
    __nv_bfloat16* asmem = smb + DD * AS; // [GR][AS]

    const int tid  = threadIdx.x;
    const int lane = tid & 31;
    const int w    = tid >> 5;
    const int row0 = bid * GR;

    // W -> bf16 smem
    if (sizeof(WT) == 4) {
        for (int i = tid * 4; i < DD * DD; i += GT * 4) {
            float4 v = *(const float4*)&((const float*)W)[i];
            int k = i >> 7, nn = i & 127;
            __nv_bfloat162* p = (__nv_bfloat162*)&wsm[k * AS + nn];
            p[0] = __floats2bfloat162_rn(v.x, v.y);
            p[1] = __floats2bfloat162_rn(v.z, v.w);
        }
    } else {
        for (int i = tid * 8; i < DD * DD; i += GT * 8) {
            uint4 v = *(const uint4*)&((const __nv_bfloat16*)W)[i];
            int k = i >> 7, nn = i & 127;
            *(uint4*)&wsm[k * AS + nn] = v;
        }
    }
    // A rows -> bf16 smem
    if (sizeof(IT) == 4) {
        for (int i = tid * 4; i < GR * DD; i += GT * 4) {
            int r = i >> 7, k = i & 127;
            float4 v = make_float4(0.f, 0.f, 0.f, 0.f);
            if (row0 + r < n) v = *(const float4*)&((const float*)A)[(size_t)(row0 + r) * DD + k];
            __nv_bfloat162* p = (__nv_bfloat162*)&asmem[r * AS + k];
            p[0] = __floats2bfloat162_rn(v.x, v.y);
            p[1] = __floats2bfloat162_rn(v.z, v.w);
        }
    } else {
        for (int i = tid * 8; i < GR * DD; i += GT * 8) {
            int r = i >> 7, k = i & 127;
            uint4 v = make_uint4(0u, 0u, 0u, 0u);
            if (row0 + r < n) v = *(const uint4*)&((const __nv_bfloat16*)A)[(size_t)(row0 + r) * DD + k];
            *(uint4*)&asmem[r * AS + k] = v;
        }
    }
    __syncthreads();

    const int group = w >> 2;           // 0/1 : row half (64 rows each)
    const int strip = w & 3;            // 0..3 : 32-col strip
    const int col0  = strip * 32;
    const int g = lane >> 2, t = lane & 3;

    // B strip -> registers
    uint32_t bf[8][8];
    {
        const int brow = lane & 15;
        const int bco  = (lane >> 4) * 8;
        #pragma unroll
        for (int kc = 0; kc < 8; kc++) {
            uint32_t ad0 = s2u(&wsm[(kc * 16 + brow) * AS + col0 + bco]);
            ldmBT4(bf[kc][0], bf[kc][1], bf[kc][2], bf[kc][3], ad0);
            uint32_t ad1 = s2u(&wsm[(kc * 16 + brow) * AS + col0 + 16 + bco]);
            ldmBT4(bf[kc][4], bf[kc][5], bf[kc][6], bf[kc][7], ad1);
        }
    }

    const int alrow = (lane & 15);
    const int acol  = (lane >> 4) * 8;

    #pragma unroll
    for (int rt = 0; rt < 4; rt++) {
        const int rbase = group * 64 + rt * 16;
        const uint32_t a_base = s2u(&asmem[(rbase + alrow) * AS + acol]);

        float acc[4][4];
        #pragma unroll
        for (int nt = 0; nt < 4; nt++)
            #pragma unroll
            for (int j = 0; j < 4; j++) acc[nt][j] = 0.f;

        #pragma unroll
        for (int kc = 0; kc < 8; kc++) {
            uint32_t a0, a1, a2, a3;
            ldmA(a0, a1, a2, a3, a_base + kc * 32);
            #pragma unroll
            for (int nt = 0; nt < 4; nt++)
                mma16816(acc[nt], a0, a1, a2, a3, bf[kc][nt * 2], bf[kc][nt * 2 + 1]);
        }

        const int r1 = row0 + rbase + g;
        const int r2 = r1 + 8;
        #pragma unroll
        for (int nt = 0; nt < 4; nt++) {
            int col = col0 + nt * 8 + t * 2;
            if (r1 < n)
                *(__nv_bfloat162*)&HB[(size_t)r1 * DD + col] =
                    __floats2bfloat162_rn(acc[nt][0], acc[nt][1]);
            if (r2 < n)
                *(__nv_bfloat162*)&HB[(size_t)r2 * DD + col] =
                    __floats2bfloat162_rn(acc[nt][2], acc[nt][3]);
        }
    }
}

// ---------------- fat kernel: gemm1 blocks + degree-count blocks ---------------
__global__ void __launch_bounds__(GT, 2)
k_fat_gemm_count(const float* __restrict__ A, const float* __restrict__ W,
                 __nv_bfloat16* __restrict__ HB, int n,
                 const int* __restrict__ dst, int* __restrict__ cnt, int gemm_blocks) {
    extern __shared__ __nv_bfloat16 smb[];
    if ((int)blockIdx.x < gemm_blocks) {
        gemm_body<float, float>(blockIdx.x, smb, A, W, HB, n);
    } else {
        int e = (blockIdx.x - gemm_blocks) * blockDim.x + threadIdx.x;
        if (e < NE) atomicAdd(&cnt[dst[e]], 1);
    }
}

// ---------------- plain GEMM kernel (layer 2: bf16 A, bf16 W) ------------------
__global__ void __launch_bounds__(GT, 2)
k_gemm_bb(const __nv_bfloat16* __restrict__ A, const __nv_bfloat16* __restrict__ W,
          __nv_bfloat16* __restrict__ HB, int n) {
    extern __shared__ __nv_bfloat16 smb[];
    gemm_body<__nv_bfloat16, __nv_bfloat16>(blockIdx.x, smb, A, W, HB, n);
}

// ---------------- W2 fp32 -> bf16 global ----------------
__global__ void k_wconv(const float* __restrict__ W, __nv_bfloat16* __restrict__ WB) {
    int i = (blockIdx.x * blockDim.x + threadIdx.x) * 4;
    if (i < DD * DD) {
        float4 v = *(const float4*)&W[i];
        __nv_bfloat162* p = (__nv_bfloat162*)&WB[i];
        p[0] = __floats2bfloat162_rn(v.x, v.y);
        p[1] = __floats2bfloat162_rn(v.z, v.w);
    }
}

// ---------------- single-block scan: offs, cursor, inv ----------------
__global__ void __launch_bounds__(SCAN_T)
k_scan(const int* __restrict__ cnt, int* __restrict__ offs,
       int* __restrict__ cursor, float* __restrict__ inv) {
    __shared__ int ssum[SCAN_T];
    int t = threadIdx.x;
    int c0 = t * SCAN_CH;
    int c1 = min(c0 + SCAN_CH, NN);
    int s = 0;
    for (int i = c0; i < c1; i++) s += cnt[i];
    ssum[t] = s;
    __syncthreads();
    for (int off = 1; off < SCAN_T; off <<= 1) {
        int u = (t >= off) ? ssum[t - off] : 0;
        __syncthreads();
        ssum[t] += u;
        __syncthreads();
    }
    int run = ssum[t] - s;   // exclusive prefix for this chunk
    for (int i = c0; i < c1; i++) {
        offs[i] = run;
        cursor[i] = run;
        inv[i] = rsqrtf((float)cnt[i] + 1.0f);
        run += cnt[i];
    }
    if (t == SCAN_T - 1) offs[NN] = NE;
}

// ---------------- scatter edges into CSR bins, precompute coef ----------------
__global__ void k_scatter(const int* __restrict__ src, const int* __restrict__ dst,
                          const float* __restrict__ inv,
                          int* __restrict__ cursor, int2* __restrict__ adj) {
    int e = blockIdx.x * blockDim.x + threadIdx.x;
    if (e >= NE) return;
    int s = src[e], d = dst[e];
    int pos = atomicAdd(&cursor[d], 1);
    adj[pos] = make_int2(s, __float_as_int(inv[s] * inv[d]));
}

// ---------------- bf16 row fragment -> float4 ----------------
__device__ __forceinline__ float4 bf2f4(uint2 u) {
    __nv_bfloat162 a = *reinterpret_cast<__nv_bfloat162*>(&u.x);
    __nv_bfloat162 b = *reinterpret_cast<__nv_bfloat162*>(&u.y);
    float2 fa = __bfloat1622float2(a);
    float2 fb = __bfloat1622float2(b);
    return make_float4(fa.x, fa.y, fb.x, fb.y);
}

// ---------------- CSR edge aggregation (direct uniform ldg, 8-wide unroll) ----
__device__ __forceinline__ float4 agg_node(
    int d, int lane,
    const int* __restrict__ offs, const int2* __restrict__ adj,
    const __nv_bfloat16* __restrict__ hb, const float* __restrict__ inv)
{
    float invd = inv[d];
    float selfc = invd * invd;
    float4 sv = bf2f4(*(const uint2*)&hb[d * DD + lane * 4]);
    float ax = sv.x * selfc, ay = sv.y * selfc, az = sv.z * selfc, aw = sv.w * selfc;
    float bx = 0.f, by = 0.f, bz = 0.f, bw = 0.f;

    int beg = offs[d], end = offs[d + 1];
    int i = beg;
    for (; i + 7 < end; i += 8) {
        int2 e0 = __ldg(&adj[i]);
        int2 e1 = __ldg(&adj[i + 1]);
        int2 e2 = __ldg(&adj[i + 2]);
        int2 e3 = __ldg(&adj[i + 3]);
        int2 e4 = __ldg(&adj[i + 4]);
        int2 e5 = __ldg(&adj[i + 5]);
        int2 e6 = __ldg(&adj[i + 6]);
        int2 e7 = __ldg(&adj[i + 7]);
        uint2 r0 = *(const uint2*)&hb[e0.x * DD + lane * 4];
        uint2 r1 = *(const uint2*)&hb[e1.x * DD + lane * 4];
        uint2 r2 = *(const uint2*)&hb[e2.x * DD + lane * 4];
        uint2 r3 = *(const uint2*)&hb[e3.x * DD + lane * 4];
        uint2 r4 = *(const uint2*)&hb[e4.x * DD + lane * 4];
        uint2 r5 = *(const uint2*)&hb[e5.x * DD + lane * 4];
        uint2 r6 = *(const uint2*)&hb[e6.x * DD + lane * 4];
        uint2 r7 = *(const uint2*)&hb[e7.x * DD + lane * 4];
        float4 v; float c;
        c = __int_as_float(e0.y); v = bf2f4(r0);
        ax += c * v.x; ay += c * v.y; az += c * v.z; aw += c * v.w;
        c = __int_as_float(e1.y); v = bf2f4(r1);
        bx += c * v.x; by += c * v.y; bz += c * v.z; bw += c * v.w;
        c = __int_as_float(e2.y); v = bf2f4(r2);
        ax += c * v.x; ay += c * v.y; az += c * v.z; aw += c * v.w;
        c = __int_as_float(e3.y); v = bf2f4(r3);
        bx += c * v.x; by += c * v.y; bz += c * v.z; bw += c * v.w;
        c = __int_as_float(e4.y); v = bf2f4(r4);
        ax += c * v.x; ay += c * v.y; az += c * v.z; aw += c * v.w;
        c = __int_as_float(e5.y); v = bf2f4(r5);
        bx += c * v.x; by += c * v.y; bz += c * v.z; bw += c * v.w;
        c = __int_as_float(e6.y); v = bf2f4(r6);
        ax += c * v.x; ay += c * v.y; az += c * v.z; aw += c * v.w;
        c = __int_as_float(e7.y); v = bf2f4(r7);
        bx += c * v.x; by += c * v.y; bz += c * v.z; bw += c * v.w;
    }
    for (; i + 1 < end; i += 2) {
        int2 e0 = __ldg(&adj[i]);
        int2 e1 = __ldg(&adj[i + 1]);
        uint2 r0 = *(const uint2*)&hb[e0.x * DD + lane * 4];
        uint2 r1 = *(const uint2*)&hb[e1.x * DD + lane * 4];
        float c0 = __int_as_float(e0.y), c1 = __int_as_float(e1.y);
        float4 v0 = bf2f4(r0), v1 = bf2f4(r1);
        ax += c0 * v0.x; ay += c0 * v0.y; az += c0 * v0.z; aw += c0 * v0.w;
        bx += c1 * v1.x; by += c1 * v1.y; bz += c1 * v1.z; bw += c1 * v1.w;
    }
    if (i < end) {
        int2 e0 = __ldg(&adj[i]);
        float c0 = __int_as_float(e0.y);
        float4 v0 = bf2f4(*(const uint2*)&hb[e0.x * DD + lane * 4]);
        ax += c0 * v0.x; ay += c0 * v0.y; az += c0 * v0.z; aw += c0 * v0.w;
    }
    return make_float4(ax + bx, ay + by, az + bz, aw + bw);
}

// ---------------- layer 1: ab = bf16(relu(aggregate + b1)) ----------------
__global__ void __launch_bounds__(256)
k_edge1(const int* __restrict__ offs, const int2* __restrict__ adj,
        const __nv_bfloat16* __restrict__ hb,
        const float* __restrict__ inv, const float* __restrict__ b,
        __nv_bfloat16* __restrict__ out) {
    int warp = (blockIdx.x * blockDim.x + threadIdx.x) >> 5;
    if (warp >= NN) return;
    int lane = threadIdx.x & 31;
    float4 a = agg_node(warp, lane, offs, adj, hb, inv);
    float4 bb = ((const float4*)b)[lane];
    uint2 ob;
    __nv_bfloat162 p0 = __floats2bfloat162_rn(fmaxf(a.x + bb.x, 0.f), fmaxf(a.y + bb.y, 0.f));
    __nv_bfloat162 p1 = __floats2bfloat162_rn(fmaxf(a.z + bb.z, 0.f), fmaxf(a.w + bb.w, 0.f));
    ob.x = *reinterpret_cast<unsigned int*>(&p0);
    ob.y = *reinterpret_cast<unsigned int*>(&p1);
    *(uint2*)&out[(size_t)warp * DD + lane * 4] = ob;
}

// ---------------- layer 2: pool += relu(aggregate + b2); also zero cnt --------
__global__ void __launch_bounds__(256)
k_edge2_pool(const int* __restrict__ offs, const int2* __restrict__ adj,
             const __nv_bfloat16* __restrict__ hb,
             const float* __restrict__ inv, const float* __restrict__ b,
             float* __restrict__ pool, int* __restrict__ cnt) {
    __shared__ float ps[DD];
    int tid = threadIdx.x;
    if (tid < DD) ps[tid] = 0.0f;
    __syncthreads();

    int gt = blockIdx.x * blockDim.x + tid;
    if (gt < NN) cnt[gt] = 0;    // reset for next graph replay

    int warp = gt >> 5;
    int lane = tid & 31;
    if (warp < NN) {
        float4 a = agg_node(warp, lane, offs, adj, hb, inv);
        float4 bb = ((const float4*)b)[lane];
        atomicAdd(&ps[lane * 4 + 0], fmaxf(a.x + bb.x, 0.f));
        atomicAdd(&ps[lane * 4 + 1], fmaxf(a.y + bb.y, 0.f));
        atomicAdd(&ps[lane * 4 + 2], fmaxf(a.z + bb.z, 0.f));
        atomicAdd(&ps[lane * 4 + 3], fmaxf(a.w + bb.w, 0.f));
    }
    __syncthreads();
    if (tid < DD) atomicAdd(&pool[tid], ps[tid]);
}

// ---------------- finalize: logits + log_softmax; also zero pool ----------------
__global__ void k_finalize(float* __restrict__ pool, const float* __restrict__ Wc,
                           const float* __restrict__ bc, float* __restrict__ out) {
    int t = threadIdx.x;             // 0..31
    float l0 = 0.f, l1 = 0.f;
    const float invn = 1.0f / (float)NN;
    #pragma unroll
    for (int j = 0; j < 4; j++) {
        int c = t * 4 + j;
        float g = pool[c] * invn;
        l0 += g * Wc[c * NC + 0];
        l1 += g * Wc[c * NC + 1];
        pool[c] = 0.0f;              // reset for next graph replay
    }
    #pragma unroll
    for (int o = 16; o > 0; o >>= 1) {
        l0 += __shfl_down_sync(0xFFFFFFFFu, l0, o);
        l1 += __shfl_down_sync(0xFFFFFFFFu, l1, o);
    }
    if (t == 0) {
        l0 += bc[0];
        l1 += bc[1];
        float m = fmaxf(l0, l1);
        float lse = m + logf(expf(l0 - m) + expf(l1 - m));
        out[0] = l0 - lse;
        out[1] = l1 - lse;
    }
}

// ---------------- launch ----------------
extern "C" void kernel_launch(void* const* d_in, const int* in_sizes, int n_in,
                              void* d_out, int out_size) {
    const float* x  = (const float*)d_in[0];
    const int*   ei = (const int*)d_in[1];
    const float* W1 = (const float*)d_in[2];
    const float* b1 = (const float*)d_in[3];
    const float* W2 = (const float*)d_in[4];
    const float* b2 = (const float*)d_in[5];
    const float* Wc = (const float*)d_in[6];
    const float* bc = (const float*)d_in[7];
    float* out = (float*)d_out;

    const int* src = ei;
    const int* dst = ei + NE;

    int *cnt, *offs, *cursor;
    int2* adj;
    float *inv, *pool;
    __nv_bfloat16 *hb, *ab, *wb;
    cudaGetSymbolAddress((void**)&cnt,    g_cnt);
    cudaGetSymbolAddress((void**)&offs,   g_offs);
    cudaGetSymbolAddress((void**)&cursor, g_cursor);
    cudaGetSymbolAddress((void**)&adj,    g_adj);
    cudaGetSymbolAddress((void**)&inv,    g_inv);
    cudaGetSymbolAddress((void**)&hb,     g_hb);
    cudaGetSymbolAddress((void**)&ab,     g_ab);
    cudaGetSymbolAddress((void**)&wb,     g_wb);
    cudaGetSymbolAddress((void**)&pool,   g_pool);

    const int smem = (DD + GR) * AS * (int)sizeof(__nv_bfloat16);
    cudaFuncSetAttribute(k_fat_gemm_count, cudaFuncAttributeMaxDynamicSharedMemorySize, smem);
    cudaFuncSetAttribute(k_gemm_bb, cudaFuncAttributeMaxDynamicSharedMemorySize, smem);

    const int gemm_grid  = (NN + GR - 1) / GR;
    const int count_grid = (NE + GT - 1) / GT;
    const int edge_grid  = (NN * 32 + 255) / 256;

    // 0: fat = layer-1 GEMM + degree count (independent work, one launch)
    k_fat_gemm_count<<<gemm_grid + count_grid, GT, smem>>>(x, W1, hb, NN, dst, cnt, gemm_grid);
    // 1-2: CSR build
    k_scan<<<1, SCAN_T>>>(cnt, offs, cursor, inv);
    k_scatter<<<(NE + 255) / 256, 256>>>(src, dst, inv, cursor, adj);
    // 3: layer-1 aggregation  <-- ncu captures this launch
    k_edge1<<<edge_grid, 256>>>(offs, adj, hb, inv, b1, ab);
    // 4: W2 -> bf16
    k_wconv<<<(DD * DD / 4 + 255) / 256, 256>>>(W2, wb);
    // 5: layer-2 GEMM (bf16 x bf16)
    k_gemm_bb<<<gemm_grid, GT, smem>>>(ab, wb, hb, NN);
    // 6: layer-2 aggregation + pool (also resets cnt)
    k_edge2_pool<<<edge_grid, 256>>>(offs, adj, hb, inv, b2, pool, cnt);
    // 7: classifier + log_softmax (also resets pool)
    k_finalize<<<1, 32>>>(pool, Wc, bc, out);
}